// round 2
// baseline (speedup 1.0000x reference)
#include <cuda_runtime.h>

#define NEGC (-10000.0f)
#define NB 32
#define NS 256
#define ND 512
#define NK 8
#define NL 64
#define NJ 36            // (k,h) pairs, h <= k
#define NCOL (NJ * NL)   // 2304
#define NROW (NB * NS)   // 8192

// Scratch
__device__ float g_effw[(size_t)NJ * NL * ND];     // 4.7 MB  [(j*64+l)][d]
__device__ float g_effb[NK * NL];
__device__ float g_P[(size_t)NROW * NCOL];         // 75.5 MB [bs][(j*64+l)]
__device__ float g_ls[(size_t)NB * NS * NK * NL];  // 16.8 MB [b][s][k][l]
__device__ float g_M[(size_t)NB * NS * NL];        // 2 MB    [b][t][l]

// ---------------------------------------------------------------------------
// Kernel A: eff_w[(k,h)][l][i] = sum_o cls_w[l][o] * conv_w[k][o][i][h]
// ---------------------------------------------------------------------------
__global__ void __launch_bounds__(256) eff_kernel(const float* __restrict__ conv_w,
                                                  const float* __restrict__ cls_w) {
    int j = blockIdx.x;
    int k = 0, rem = j;
    while (rem > k) { rem -= (k + 1); k++; }
    int h = rem;
    int i0 = blockIdx.y * 64;

    __shared__ float As[32][65];
    __shared__ float Bs[64][33];

    int tid = threadIdx.x;
    int lx = tid & 15;
    int ly = tid >> 4;
    float acc[4][4] = {};

    for (int o0 = 0; o0 < ND; o0 += 32) {
        for (int idx = tid; idx < 32 * 64; idx += 256) {
            int o = idx >> 6, i = idx & 63;
            As[o][i] = conv_w[(((size_t)k * ND + (o0 + o)) * ND + (i0 + i)) * NK + h];
        }
        for (int idx = tid; idx < 64 * 32; idx += 256) {
            int l = idx >> 5, o = idx & 31;
            Bs[l][o] = cls_w[l * ND + o0 + o];
        }
        __syncthreads();
#pragma unroll
        for (int o = 0; o < 32; o++) {
            float a[4], bb[4];
#pragma unroll
            for (int u = 0; u < 4; u++) a[u] = As[o][lx + 16 * u];
#pragma unroll
            for (int u = 0; u < 4; u++) bb[u] = Bs[ly + 16 * u][o];
#pragma unroll
            for (int y = 0; y < 4; y++)
#pragma unroll
                for (int x = 0; x < 4; x++) acc[y][x] += a[x] * bb[y];
        }
        __syncthreads();
    }
#pragma unroll
    for (int y = 0; y < 4; y++) {
        int l = ly + 16 * y;
#pragma unroll
        for (int x = 0; x < 4; x++) {
            int i = i0 + lx + 16 * x;
            g_effw[((size_t)j * NL + l) * ND + i] = acc[y][x];
        }
    }
}

__global__ void effb_kernel(const float* __restrict__ cls_w,
                            const float* __restrict__ conv_b,
                            const float* __restrict__ cls_b) {
    int tid = threadIdx.x;
    int k = tid >> 6, l = tid & 63;
    float s = 0.f;
    for (int o = 0; o < ND; o++) s += cls_w[l * ND + o] * conv_b[k * ND + o];
    g_effb[k * NL + l] = s + cls_b[l];
}

// ---------------------------------------------------------------------------
// Kernel B: P = wr(8192x512) @ effw^T(512x2304), fp32 via packed FFMA2.
// Tile 128x64, 256 threads, micro 8x4, DK=16 double-buffered cp.async.
// ---------------------------------------------------------------------------
#define DKC 16
#define SDK 20   // padded d-stride (floats); 20*4=80B keeps 16B alignment

__global__ void __launch_bounds__(256) gemm_kernel(const float* __restrict__ A) {
    __shared__ __align__(16) float As[2][128 * SDK];  // [m][d]
    __shared__ __align__(16) float Bs[2][64 * SDK];   // [n][d]

    int m0 = blockIdx.x * 128;
    int n0 = blockIdx.y * 64;
    int tid = threadIdx.x;
    int tx = tid & 15, ty = tid >> 4;
    int crow = tid >> 2;          // 0..63
    int cd4 = (tid & 3) * 4;      // 0,4,8,12

    const float* Bg = g_effw;
    unsigned sA0 = (unsigned)__cvta_generic_to_shared(&As[0][0]);
    unsigned sB0 = (unsigned)__cvta_generic_to_shared(&Bs[0][0]);

    auto issue_chunk = [&](int c, int buf) {
        unsigned aD = sA0 + (unsigned)(buf * 128 * SDK * 4 + (crow * SDK + cd4) * 4);
        const float* aS = A + (size_t)(m0 + crow) * ND + c * DKC + cd4;
#pragma unroll
        for (int it = 0; it < 2; ++it) {
            asm volatile("cp.async.ca.shared.global [%0], [%1], 16;"
                         :: "r"(aD + (unsigned)(it * 64 * SDK * 4)),
                            "l"(aS + (size_t)it * 64 * ND));
        }
        unsigned bD = sB0 + (unsigned)(buf * 64 * SDK * 4 + (crow * SDK + cd4) * 4);
        const float* bS = Bg + (size_t)(n0 + crow) * ND + c * DKC + cd4;
        asm volatile("cp.async.ca.shared.global [%0], [%1], 16;"
                     :: "r"(bD), "l"(bS));
    };

    unsigned long long acc[8][4] = {};

    issue_chunk(0, 0);
    asm volatile("cp.async.commit_group;");

    const int NCHUNK = ND / DKC;  // 32
    for (int c = 0; c < NCHUNK; ++c) {
        if (c + 1 < NCHUNK) issue_chunk(c + 1, (c + 1) & 1);
        asm volatile("cp.async.commit_group;");
        asm volatile("cp.async.wait_group 1;" ::: "memory");
        __syncthreads();

        const float* as = &As[c & 1][ty * 8 * SDK];
        const float* bs = &Bs[c & 1][tx * 4 * SDK];
#pragma unroll
        for (int dd = 0; dd < DKC; dd += 4) {
            union U4 { float4 f; unsigned long long u[2]; };
            U4 ua[8], ub[4];
#pragma unroll
            for (int mi = 0; mi < 8; ++mi) ua[mi].f = *(const float4*)(as + mi * SDK + dd);
#pragma unroll
            for (int ni = 0; ni < 4; ++ni) ub[ni].f = *(const float4*)(bs + ni * SDK + dd);
#pragma unroll
            for (int mi = 0; mi < 8; ++mi)
#pragma unroll
                for (int ni = 0; ni < 4; ++ni) {
                    asm("fma.rn.f32x2 %0, %1, %2, %0;"
                        : "+l"(acc[mi][ni]) : "l"(ua[mi].u[0]), "l"(ub[ni].u[0]));
                    asm("fma.rn.f32x2 %0, %1, %2, %0;"
                        : "+l"(acc[mi][ni]) : "l"(ua[mi].u[1]), "l"(ub[ni].u[1]));
                }
        }
        __syncthreads();
    }

#pragma unroll
    for (int mi = 0; mi < 8; ++mi) {
        float4 o;
        float* op = &o.x;
#pragma unroll
        for (int ni = 0; ni < 4; ++ni) {
            union { unsigned long long u; float2 f; } t;
            t.u = acc[mi][ni];
            op[ni] = t.f.x + t.f.y;
        }
        *(float4*)&g_P[(size_t)(m0 + ty * 8 + mi) * NCOL + n0 + tx * 4] = o;
    }
}

// ---------------------------------------------------------------------------
// Kernel B2: gather  ls[b,s,k,l] = sum_h P[bs-k+h][(jb+h)*64+l] + effb, masked
// ---------------------------------------------------------------------------
__global__ void __launch_bounds__(256) gather_kernel(const int* __restrict__ mask) {
    int bs = blockIdx.x;
    int s = bs & (NS - 1);
    int tid = threadIdx.x;
    int l = tid & 63;
    int k0 = tid >> 6;
    int mv = mask[bs];
#pragma unroll
    for (int u = 0; u < 2; ++u) {
        int k = k0 + 4 * u;
        float v = NEGC;
        if (mv == 1 && k <= s && l != 0) {
            float a = g_effb[k * NL + l];
            int jb = k * (k + 1) / 2;
            for (int h = 0; h <= k; ++h)
                a += g_P[(size_t)(bs - k + h) * NCOL + (jb + h) * NL + l];
            v = a;
        }
        g_ls[((size_t)bs * NK + k) * NL + l] = v;
    }
}

// ---------------------------------------------------------------------------
// Kernel C: semi-CRF DP, 1 block/batch, 1 barrier/step, stale-max normalize.
// ---------------------------------------------------------------------------
__global__ void __launch_bounds__(256) dp_kernel(const int* __restrict__ mask,
                                                 const float* __restrict__ T,
                                                 const float* __restrict__ TFB,
                                                 const float* __restrict__ TTE,
                                                 float* __restrict__ out) {
    int b = blockIdx.x;
    int tid = threadIdx.x;
    int lane = tid & 31, warp = tid >> 5;
    int l = tid >> 2, q = tid & 3;

    __shared__ __align__(16) float sLs[4][512];
    __shared__ float sMring[8][65];
    __shared__ float sE[2][64];
    __shared__ float sWmax[2][8];
    __shared__ float sTFB[64], sTTE[64], sRed[8];
    __shared__ float sMaxS;
    __shared__ int sMask[256], sLen;

    float rT[16];
#pragma unroll
    for (int jj = 0; jj < 16; ++jj) rT[jj] = __expf(T[l * NL + q * 16 + jj]);
    if (tid < 64) {
        sTFB[tid] = TFB[tid];
        sTTE[tid] = TTE[tid];
#pragma unroll
        for (int i = 0; i < 8; ++i) sMring[i][tid] = NEGC;
    }
    sMask[tid] = mask[b * NS + tid];
    if (tid == 0) sLen = 0;

    const float* lsb = g_ls + (size_t)b * NS * (NK * NL);
    unsigned sls = (unsigned)__cvta_generic_to_shared(&sLs[0][0]);
#pragma unroll
    for (int p = 0; p < 3; ++p) {
        asm volatile("cp.async.ca.shared.global [%0], [%1], 8;"
                     :: "r"(sls + (unsigned)((p * 512 + tid * 2) * 4)),
                        "l"(lsb + p * 512 + tid * 2));
        asm volatile("cp.async.commit_group;");
    }
    asm volatile("cp.async.wait_group 2;" ::: "memory");
    __syncthreads();

    float N = 0.f;
    for (int t = 0; t < NS; ++t) {
        // ---- phase 1 ----
        int mv = sMask[t];
        const float* lst = &sLs[t & 3][0];
        float v0, v1;
        {
            int k = q;
            float lsv = lst[k * 64 + l];
            v0 = (k == t) ? lsv + sTFB[l]
               : (k > t)  ? NEGC
               : (mv ? lsv + sMring[(t - 1 - k) & 7][l] : NEGC);
        }
        {
            int k = q + 4;
            float lsv = lst[k * 64 + l];
            v1 = (k == t) ? lsv + sTFB[l]
               : (k > t)  ? NEGC
               : (mv ? lsv + sMring[(t - 1 - k) & 7][l] : NEGC);
        }
        float e = __expf(v0 - N) + __expf(v1 - N);
        e += __shfl_xor_sync(~0u, e, 1);
        e += __shfl_xor_sync(~0u, e, 2);
        if (q == 0) sE[t & 1][l] = e;
        float wm = e;
        wm = fmaxf(wm, __shfl_xor_sync(~0u, wm, 4));
        wm = fmaxf(wm, __shfl_xor_sync(~0u, wm, 8));
        wm = fmaxf(wm, __shfl_xor_sync(~0u, wm, 16));
        if (lane == 0) sWmax[t & 1][warp] = wm;

        if (t + 3 < NS) {
            asm volatile("cp.async.ca.shared.global [%0], [%1], 8;"
                         :: "r"(sls + (unsigned)((((t + 3) & 3) * 512 + tid * 2) * 4)),
                            "l"(lsb + (size_t)(t + 3) * 512 + tid * 2));
        }
        asm volatile("cp.async.commit_group;");
        asm volatile("cp.async.wait_group 2;" ::: "memory");
        __syncthreads();

        // ---- phase 2 ----
        float p = 0.f;
        const float* se = &sE[t & 1][q * 16];
#pragma unroll
        for (int jj = 0; jj < 16; ++jj) p += rT[jj] * se[jj];
        p += __shfl_xor_sync(~0u, p, 1);
        p += __shfl_xor_sync(~0u, p, 2);
        float Mnew = fmaxf(__logf(p) + N, -1e30f);
        if (q == 0) {
            sMring[t & 7][l] = Mnew;
            g_M[((size_t)b * NS + t) * NL + l] = Mnew;
        }
        float me = sWmax[t & 1][0];
#pragma unroll
        for (int w = 1; w < 8; ++w) me = fmaxf(me, sWmax[t & 1][w]);
        N += __logf(fmaxf(me, 1e-30f));
        __syncwarp();
    }

    // ---- finalization ----
    {
        int mvv = sMask[tid];
#pragma unroll
        for (int o = 16; o > 0; o >>= 1) mvv += __shfl_xor_sync(~0u, mvv, o);
        if (lane == 0) atomicAdd(&sLen, mvv);
    }
    __syncthreads();
    int len = sLen;

    float vv[2];
#pragma unroll
    for (int u = 0; u < 2; ++u) {
        int k = q + 4 * u;
        int tk = len - 1 - k;
        int tix = (tk >= 0) ? tk : (NS - 1);
        float lsv = lsb[(size_t)tix * (NK * NL) + k * NL + l];
        float gv;
        if (k == tix)      gv = lsv + sTFB[l];
        else if (k > tix)  gv = NEGC;
        else               gv = (sMask[tix] == 1)
                                  ? lsv + g_M[((size_t)b * NS + (tix - 1 - k)) * NL + l]
                                  : NEGC;
        vv[u] = gv + sTTE[l];
    }
    float mx = fmaxf(vv[0], vv[1]);
#pragma unroll
    for (int o = 16; o > 0; o >>= 1) mx = fmaxf(mx, __shfl_xor_sync(~0u, mx, o));
    if (lane == 0) sRed[warp] = mx;
    __syncthreads();
    if (tid == 0) {
        float m = sRed[0];
#pragma unroll
        for (int w = 1; w < 8; ++w) m = fmaxf(m, sRed[w]);
        sMaxS = m;
    }
    __syncthreads();
    float gm = sMaxS;
    float e2 = __expf(vv[0] - gm) + __expf(vv[1] - gm);
#pragma unroll
    for (int o = 16; o > 0; o >>= 1) e2 += __shfl_xor_sync(~0u, e2, o);
    if (lane == 0) sRed[warp] = e2;
    __syncthreads();
    if (tid == 0) {
        float ssum = 0.f;
#pragma unroll
        for (int w = 0; w < 8; ++w) ssum += sRed[w];
        out[b] = __logf(ssum) + gm;
    }
}

// ---------------------------------------------------------------------------
extern "C" void kernel_launch(void* const* d_in, const int* in_sizes, int n_in,
                              void* d_out, int out_size) {
    const float* word_rep = (const float*)d_in[0];
    const int*   mask     = (const int*)  d_in[1];
    const float* conv_w   = (const float*)d_in[2];
    const float* conv_b   = (const float*)d_in[3];
    const float* cls_w    = (const float*)d_in[4];
    const float* cls_b    = (const float*)d_in[5];
    const float* T        = (const float*)d_in[6];
    const float* TFB      = (const float*)d_in[7];
    const float* TTE      = (const float*)d_in[8];
    float* out = (float*)d_out;

    eff_kernel<<<dim3(NJ, 8), 256>>>(conv_w, cls_w);
    effb_kernel<<<1, NK * NL>>>(cls_w, conv_b, cls_b);
    gemm_kernel<<<dim3(NROW / 128, NCOL / 64), 256>>>(word_rep);
    gather_kernel<<<NROW, 256>>>(mask);
    dp_kernel<<<NB, 256>>>(mask, T, TFB, TTE, out);
}

// round 4
// speedup vs baseline: 2.2251x; 2.2251x over previous
#include <cuda_runtime.h>
#include <cuda_bf16.h>
#include <cstdint>

#define NEGC (-10000.0f)
#define NB 32
#define NS 256
#define ND 512
#define NK 8
#define NL 64
#define NJ 36            // (k,h) pairs, h <= k
#define NCOL (NJ * NL)   // 2304
#define NROW (NB * NS)   // 8192
#define KT   1536        // 3*ND concatenated split-bf16 K
#define BKC  64          // bf16 per k-chunk (one SW128 atom row)
#define NCH  (KT / BKC)  // 24

// Scratch
__device__ float g_effw[(size_t)NJ * NL * ND];
__device__ float g_effb[NK * NL];
__device__ float g_P[(size_t)NROW * NCOL];
__device__ float g_ls[(size_t)NB * NS * NK * NL];
__device__ float g_M[(size_t)NB * NS * NL];
__device__ __nv_bfloat16 g_Ab[(size_t)NROW * KT];   // 25.2 MB
__device__ __nv_bfloat16 g_Bb[(size_t)NCOL * KT];   // 7.1 MB

__device__ __forceinline__ uint32_t smem_u32(const void* p) {
    uint32_t a;
    asm("{ .reg .u64 t; cvta.to.shared.u64 t, %1; cvt.u32.u64 %0, t; }" : "=r"(a) : "l"(p));
    return a;
}

// ---------------------------------------------------------------------------
// Kernel A: eff_w[(k,h)][l][i] = sum_o cls_w[l][o] * conv_w[k][o][i][h]
// ---------------------------------------------------------------------------
__global__ void __launch_bounds__(256) eff_kernel(const float* __restrict__ conv_w,
                                                  const float* __restrict__ cls_w) {
    int j = blockIdx.x;
    int k = 0, rem = j;
    while (rem > k) { rem -= (k + 1); k++; }
    int h = rem;
    int i0 = blockIdx.y * 64;

    __shared__ float As[32][65];
    __shared__ float Bs[64][33];

    int tid = threadIdx.x;
    int lx = tid & 15;
    int ly = tid >> 4;
    float acc[4][4] = {};

    for (int o0 = 0; o0 < ND; o0 += 32) {
        for (int idx = tid; idx < 32 * 64; idx += 256) {
            int o = idx >> 6, i = idx & 63;
            As[o][i] = conv_w[(((size_t)k * ND + (o0 + o)) * ND + (i0 + i)) * NK + h];
        }
        for (int idx = tid; idx < 64 * 32; idx += 256) {
            int l = idx >> 5, o = idx & 31;
            Bs[l][o] = cls_w[l * ND + o0 + o];
        }
        __syncthreads();
#pragma unroll
        for (int o = 0; o < 32; o++) {
            float a[4], bb[4];
#pragma unroll
            for (int u = 0; u < 4; u++) a[u] = As[o][lx + 16 * u];
#pragma unroll
            for (int u = 0; u < 4; u++) bb[u] = Bs[ly + 16 * u][o];
#pragma unroll
            for (int y = 0; y < 4; y++)
#pragma unroll
                for (int x = 0; x < 4; x++) acc[y][x] += a[x] * bb[y];
        }
        __syncthreads();
    }
#pragma unroll
    for (int y = 0; y < 4; y++) {
        int l = ly + 16 * y;
#pragma unroll
        for (int x = 0; x < 4; x++) {
            int i = i0 + lx + 16 * x;
            g_effw[((size_t)j * NL + l) * ND + i] = acc[y][x];
        }
    }
}

__global__ void effb_kernel(const float* __restrict__ cls_w,
                            const float* __restrict__ conv_b,
                            const float* __restrict__ cls_b) {
    int tid = threadIdx.x;
    int k = tid >> 6, l = tid & 63;
    float s = 0.f;
    for (int o = 0; o < ND; o++) s += cls_w[l * ND + o] * conv_b[k * ND + o];
    g_effb[k * NL + l] = s + cls_b[l];
}

// ---------------------------------------------------------------------------
// Split fp32 -> concatenated (hi, lo) bf16:
//   Abig row = [Ah(512) | Al(512) | Ah(512)],  Bbig row = [Bh | Bh | Bl]
// ---------------------------------------------------------------------------
__global__ void __launch_bounds__(256) cvtA_kernel(const float* __restrict__ src) {
    size_t i = (size_t)blockIdx.x * 256 + threadIdx.x;   // pair index
    int row = (int)(i >> 8);          // ND/2 = 256 pairs/row
    int cp = (int)(i & 255);
    float2 v = ((const float2*)src)[i];
    __nv_bfloat16 hx = __float2bfloat16(v.x), hy = __float2bfloat16(v.y);
    __nv_bfloat16 lx = __float2bfloat16(v.x - __bfloat162float(hx));
    __nv_bfloat16 ly = __float2bfloat16(v.y - __bfloat162float(hy));
    __nv_bfloat162* dst = (__nv_bfloat162*)g_Ab + (size_t)row * (KT / 2);
    __nv_bfloat162 hi(hx, hy), lo(lx, ly);
    dst[cp] = hi;
    dst[256 + cp] = lo;
    dst[512 + cp] = hi;
}
__global__ void __launch_bounds__(256) cvtB_kernel() {
    size_t i = (size_t)blockIdx.x * 256 + threadIdx.x;
    int row = (int)(i >> 8);
    int cp = (int)(i & 255);
    float2 v = ((const float2*)g_effw)[i];
    __nv_bfloat16 hx = __float2bfloat16(v.x), hy = __float2bfloat16(v.y);
    __nv_bfloat16 lx = __float2bfloat16(v.x - __bfloat162float(hx));
    __nv_bfloat16 ly = __float2bfloat16(v.y - __bfloat162float(hy));
    __nv_bfloat162* dst = (__nv_bfloat162*)g_Bb + (size_t)row * (KT / 2);
    __nv_bfloat162 hi(hx, hy), lo(lx, ly);
    dst[cp] = hi;
    dst[256 + cp] = hi;
    dst[512 + cp] = lo;
}

// ---------------------------------------------------------------------------
// Kernel B: P = Abig(8192x1536) @ Bbig^T(2304x1536) bf16->fp32 via mma.sync.
// CTA 128x128, BK=64, 3-stage cp.async, SW128 smem, 8 warps (4m x 2n).
// ---------------------------------------------------------------------------
#define STG_B 32768   // bytes per stage: A 16KB + B 16KB
#define SMEM_MMA (3 * STG_B)

__global__ void __launch_bounds__(256) mma_kernel() {
    extern __shared__ __align__(1024) char sm[];
    int tid = threadIdx.x, wid = tid >> 5, lane = tid & 31;
    int m0 = blockIdx.x * 128, n0 = blockIdx.y * 128;
    uint32_t sb = smem_u32(sm);

    auto load = [&](int c) {
        uint32_t abase = sb + (c % 3) * STG_B;
        const __nv_bfloat16* Ag = g_Ab + (size_t)m0 * KT + c * BKC;
        const __nv_bfloat16* Bg = g_Bb + (size_t)n0 * KT + c * BKC;
#pragma unroll
        for (int i = 0; i < 4; ++i) {
            int idx = tid + 256 * i;
            int r = idx >> 3, c16 = idx & 7;
            uint32_t sw = (uint32_t)(r * 128 + ((c16 ^ (r & 7)) * 16));
            asm volatile("cp.async.ca.shared.global [%0], [%1], 16;"
                         :: "r"(abase + sw), "l"(Ag + (size_t)r * KT + c16 * 8));
            asm volatile("cp.async.ca.shared.global [%0], [%1], 16;"
                         :: "r"(abase + 16384 + sw), "l"(Bg + (size_t)r * KT + c16 * 8));
        }
        asm volatile("cp.async.commit_group;");
    };

    load(0); load(1);

    float acc[2][8][4] = {};
    int mw = (wid >> 1) * 32, nw = (wid & 1) * 64;

    for (int c = 0; c < NCH; ++c) {
        asm volatile("cp.async.wait_group 1;" ::: "memory");
        __syncthreads();
        if (c + 2 < NCH) load(c + 2);
        else asm volatile("cp.async.commit_group;");

        uint32_t Ab = sb + (c % 3) * STG_B;
        uint32_t Bb = Ab + 16384;
#pragma unroll
        for (int ks = 0; ks < 4; ++ks) {
            uint32_t ar[2][4], br[4][4];
            int c16 = ks * 2 + (lane >> 4);
#pragma unroll
            for (int mt = 0; mt < 2; ++mt) {
                int row = mw + mt * 16 + (lane & 15);
                uint32_t addr = Ab + row * 128 + ((c16 ^ (row & 7)) * 16);
                asm volatile("ldmatrix.sync.aligned.m8n8.x4.shared.b16 {%0,%1,%2,%3}, [%4];"
                             : "=r"(ar[mt][0]), "=r"(ar[mt][1]), "=r"(ar[mt][2]), "=r"(ar[mt][3])
                             : "r"(addr));
            }
#pragma unroll
            for (int g = 0; g < 4; ++g) {
                int row = nw + g * 16 + (lane & 15);
                uint32_t addr = Bb + row * 128 + ((c16 ^ (row & 7)) * 16);
                asm volatile("ldmatrix.sync.aligned.m8n8.x4.shared.b16 {%0,%1,%2,%3}, [%4];"
                             : "=r"(br[g][0]), "=r"(br[g][1]), "=r"(br[g][2]), "=r"(br[g][3])
                             : "r"(addr));
            }
#pragma unroll
            for (int mt = 0; mt < 2; ++mt)
#pragma unroll
                for (int nn = 0; nn < 8; ++nn) {
                    int g = nn >> 1, s = nn & 1;
                    asm volatile(
                        "mma.sync.aligned.m16n8k16.row.col.f32.bf16.bf16.f32 "
                        "{%0,%1,%2,%3},{%4,%5,%6,%7},{%8,%9},{%0,%1,%2,%3};"
                        : "+f"(acc[mt][nn][0]), "+f"(acc[mt][nn][1]),
                          "+f"(acc[mt][nn][2]), "+f"(acc[mt][nn][3])
                        : "r"(ar[mt][0]), "r"(ar[mt][1]), "r"(ar[mt][2]), "r"(ar[mt][3]),
                          "r"(br[g][s]), "r"(br[g][s + 2]));
                }
        }
    }

#pragma unroll
    for (int mt = 0; mt < 2; ++mt) {
        int r0 = m0 + mw + mt * 16 + (lane >> 2);
#pragma unroll
        for (int nn = 0; nn < 8; ++nn) {
            int col = n0 + nw + nn * 8 + (lane & 3) * 2;
            *(float2*)&g_P[(size_t)r0 * NCOL + col] =
                make_float2(acc[mt][nn][0], acc[mt][nn][1]);
            *(float2*)&g_P[(size_t)(r0 + 8) * NCOL + col] =
                make_float2(acc[mt][nn][2], acc[mt][nn][3]);
        }
    }
}

// ---------------------------------------------------------------------------
// Kernel B2: gather  ls[b,s,k,l] = sum_h P[bs-k+h][(jb+h)*64+l] + effb, masked
// ---------------------------------------------------------------------------
__global__ void __launch_bounds__(256) gather_kernel(const int* __restrict__ mask) {
    int bs = blockIdx.x;
    int s = bs & (NS - 1);
    int tid = threadIdx.x;
    int l = tid & 63;
    int k0 = tid >> 6;
    int mv = mask[bs];
#pragma unroll
    for (int u = 0; u < 2; ++u) {
        int k = k0 + 4 * u;
        float v = NEGC;
        if (mv == 1 && k <= s && l != 0) {
            float a = g_effb[k * NL + l];
            int jb = k * (k + 1) / 2;
            for (int h = 0; h <= k; ++h)
                a += g_P[(size_t)(bs - k + h) * NCOL + (jb + h) * NL + l];
            v = a;
        }
        g_ls[((size_t)bs * NK + k) * NL + l] = v;
    }
}

// ---------------------------------------------------------------------------
// Kernel C: semi-CRF DP, 1 block/batch, 1 barrier/step, stale-max normalize.
// ---------------------------------------------------------------------------
__global__ void __launch_bounds__(256) dp_kernel(const int* __restrict__ mask,
                                                 const float* __restrict__ T,
                                                 const float* __restrict__ TFB,
                                                 const float* __restrict__ TTE,
                                                 float* __restrict__ out) {
    int b = blockIdx.x;
    int tid = threadIdx.x;
    int lane = tid & 31, warp = tid >> 5;
    int l = tid >> 2, q = tid & 3;

    __shared__ __align__(16) float sLs[4][512];
    __shared__ float sMring[8][65];
    __shared__ float sE[2][64];
    __shared__ float sWmax[2][8];
    __shared__ float sTFB[64], sTTE[64], sRed[8];
    __shared__ float sMaxS;
    __shared__ int sMask[256], sLen;

    float rT[16];
#pragma unroll
    for (int jj = 0; jj < 16; ++jj) rT[jj] = __expf(T[l * NL + q * 16 + jj]);
    if (tid < 64) {
        sTFB[tid] = TFB[tid];
        sTTE[tid] = TTE[tid];
#pragma unroll
        for (int i = 0; i < 8; ++i) sMring[i][tid] = NEGC;
    }
    sMask[tid] = mask[b * NS + tid];
    if (tid == 0) sLen = 0;

    const float* lsb = g_ls + (size_t)b * NS * (NK * NL);
    unsigned sls = (unsigned)__cvta_generic_to_shared(&sLs[0][0]);
#pragma unroll
    for (int p = 0; p < 3; ++p) {
        asm volatile("cp.async.ca.shared.global [%0], [%1], 8;"
                     :: "r"(sls + (unsigned)((p * 512 + tid * 2) * 4)),
                        "l"(lsb + p * 512 + tid * 2));
        asm volatile("cp.async.commit_group;");
    }
    asm volatile("cp.async.wait_group 2;" ::: "memory");
    __syncthreads();

    float N = 0.f;
    for (int t = 0; t < NS; ++t) {
        int mv = sMask[t];
        const float* lst = &sLs[t & 3][0];
        float v0, v1;
        {
            int k = q;
            float lsv = lst[k * 64 + l];
            v0 = (k == t) ? lsv + sTFB[l]
               : (k > t)  ? NEGC
               : (mv ? lsv + sMring[(t - 1 - k) & 7][l] : NEGC);
        }
        {
            int k = q + 4;
            float lsv = lst[k * 64 + l];
            v1 = (k == t) ? lsv + sTFB[l]
               : (k > t)  ? NEGC
               : (mv ? lsv + sMring[(t - 1 - k) & 7][l] : NEGC);
        }
        float e = __expf(v0 - N) + __expf(v1 - N);
        e += __shfl_xor_sync(~0u, e, 1);
        e += __shfl_xor_sync(~0u, e, 2);
        if (q == 0) sE[t & 1][l] = e;
        float wm = e;
        wm = fmaxf(wm, __shfl_xor_sync(~0u, wm, 4));
        wm = fmaxf(wm, __shfl_xor_sync(~0u, wm, 8));
        wm = fmaxf(wm, __shfl_xor_sync(~0u, wm, 16));
        if (lane == 0) sWmax[t & 1][warp] = wm;

        if (t + 3 < NS) {
            asm volatile("cp.async.ca.shared.global [%0], [%1], 8;"
                         :: "r"(sls + (unsigned)((((t + 3) & 3) * 512 + tid * 2) * 4)),
                            "l"(lsb + (size_t)(t + 3) * 512 + tid * 2));
        }
        asm volatile("cp.async.commit_group;");
        asm volatile("cp.async.wait_group 2;" ::: "memory");
        __syncthreads();

        float p = 0.f;
        const float* se = &sE[t & 1][q * 16];
#pragma unroll
        for (int jj = 0; jj < 16; ++jj) p += rT[jj] * se[jj];
        p += __shfl_xor_sync(~0u, p, 1);
        p += __shfl_xor_sync(~0u, p, 2);
        float Mnew = fmaxf(__logf(p) + N, -1e30f);
        if (q == 0) {
            sMring[t & 7][l] = Mnew;
            g_M[((size_t)b * NS + t) * NL + l] = Mnew;
        }
        float me = sWmax[t & 1][0];
#pragma unroll
        for (int w = 1; w < 8; ++w) me = fmaxf(me, sWmax[t & 1][w]);
        N += __logf(fmaxf(me, 1e-30f));
        __syncwarp();
    }

    {
        int mvv = sMask[tid];
#pragma unroll
        for (int o = 16; o > 0; o >>= 1) mvv += __shfl_xor_sync(~0u, mvv, o);
        if (lane == 0) atomicAdd(&sLen, mvv);
    }
    __syncthreads();
    int len = sLen;

    float vv[2];
#pragma unroll
    for (int u = 0; u < 2; ++u) {
        int k = q + 4 * u;
        int tk = len - 1 - k;
        int tix = (tk >= 0) ? tk : (NS - 1);
        float lsv = lsb[(size_t)tix * (NK * NL) + k * NL + l];
        float gv;
        if (k == tix)      gv = lsv + sTFB[l];
        else if (k > tix)  gv = NEGC;
        else               gv = (sMask[tix] == 1)
                                  ? lsv + g_M[((size_t)b * NS + (tix - 1 - k)) * NL + l]
                                  : NEGC;
        vv[u] = gv + sTTE[l];
    }
    float mx = fmaxf(vv[0], vv[1]);
#pragma unroll
    for (int o = 16; o > 0; o >>= 1) mx = fmaxf(mx, __shfl_xor_sync(~0u, mx, o));
    if (lane == 0) sRed[warp] = mx;
    __syncthreads();
    if (tid == 0) {
        float m = sRed[0];
#pragma unroll
        for (int w = 1; w < 8; ++w) m = fmaxf(m, sRed[w]);
        sMaxS = m;
    }
    __syncthreads();
    float gm = sMaxS;
    float e2 = __expf(vv[0] - gm) + __expf(vv[1] - gm);
#pragma unroll
    for (int o = 16; o > 0; o >>= 1) e2 += __shfl_xor_sync(~0u, e2, o);
    if (lane == 0) sRed[warp] = e2;
    __syncthreads();
    if (tid == 0) {
        float ssum = 0.f;
#pragma unroll
        for (int w = 0; w < 8; ++w) ssum += sRed[w];
        out[b] = __logf(ssum) + gm;
    }
}

// ---------------------------------------------------------------------------
extern "C" void kernel_launch(void* const* d_in, const int* in_sizes, int n_in,
                              void* d_out, int out_size) {
    const float* word_rep = (const float*)d_in[0];
    const int*   mask     = (const int*)  d_in[1];
    const float* conv_w   = (const float*)d_in[2];
    const float* conv_b   = (const float*)d_in[3];
    const float* cls_w    = (const float*)d_in[4];
    const float* cls_b    = (const float*)d_in[5];
    const float* T        = (const float*)d_in[6];
    const float* TFB      = (const float*)d_in[7];
    const float* TTE      = (const float*)d_in[8];
    float* out = (float*)d_out;

    cudaFuncSetAttribute(mma_kernel, cudaFuncAttributeMaxDynamicSharedMemorySize,
                         SMEM_MMA);

    eff_kernel<<<dim3(NJ, 8), 256>>>(conv_w, cls_w);
    effb_kernel<<<1, NK * NL>>>(cls_w, conv_b, cls_b);
    cvtA_kernel<<<(NROW * ND / 2) / 256, 256>>>(word_rep);
    cvtB_kernel<<<(NCOL * ND / 2) / 256, 256>>>();
    mma_kernel<<<dim3(NROW / 128, NCOL / 128), 256, SMEM_MMA>>>();
    gather_kernel<<<NROW, 256>>>(mask);
    dp_kernel<<<NB, 256>>>(mask, T, TFB, TTE, out);
}

// round 5
// speedup vs baseline: 2.8922x; 1.2998x over previous
#include <cuda_runtime.h>
#include <cuda_bf16.h>
#include <cstdint>

#define NEGC (-10000.0f)
#define NB 32
#define NS 256
#define ND 512
#define NK 8
#define NL 64
#define NJ 36            // (k,h) pairs, h <= k
#define NROW (NB * NS)   // 8192

// Scratch
__device__ float g_effw[(size_t)NJ * NL * ND];
__device__ float g_effb[NK * NL];
__device__ float g_ls[(size_t)NB * NS * NK * NL];  // 16.8 MB [bs][k][l]
__device__ float g_M[(size_t)NB * NS * NL];        // 2 MB
__device__ __nv_bfloat16 g_Ab[(size_t)NROW * ND];            // 8.4 MB
__device__ __nv_bfloat16 g_Bls[(size_t)NK * NK * NL * ND];   // 4.2 MB [k][delta][l][d]

__device__ __forceinline__ uint32_t smem_u32(const void* p) {
    uint32_t a;
    asm("{ .reg .u64 t; cvta.to.shared.u64 t, %1; cvt.u32.u64 %0, t; }" : "=r"(a) : "l"(p));
    return a;
}

// ---------------------------------------------------------------------------
// Kernel A: eff_w[(k,h)][l][i] = sum_o cls_w[l][o] * conv_w[k][o][i][h]
// ---------------------------------------------------------------------------
__global__ void __launch_bounds__(256) eff_kernel(const float* __restrict__ conv_w,
                                                  const float* __restrict__ cls_w) {
    int j = blockIdx.x;
    int k = 0, rem = j;
    while (rem > k) { rem -= (k + 1); k++; }
    int h = rem;
    int i0 = blockIdx.y * 64;

    __shared__ float As[32][65];
    __shared__ float Bs[64][33];

    int tid = threadIdx.x;
    int lx = tid & 15;
    int ly = tid >> 4;
    float acc[4][4] = {};

    for (int o0 = 0; o0 < ND; o0 += 32) {
        for (int idx = tid; idx < 32 * 64; idx += 256) {
            int o = idx >> 6, i = idx & 63;
            As[o][i] = conv_w[(((size_t)k * ND + (o0 + o)) * ND + (i0 + i)) * NK + h];
        }
        for (int idx = tid; idx < 64 * 32; idx += 256) {
            int l = idx >> 5, o = idx & 31;
            Bs[l][o] = cls_w[l * ND + o0 + o];
        }
        __syncthreads();
#pragma unroll
        for (int o = 0; o < 32; o++) {
            float a[4], bb[4];
#pragma unroll
            for (int u = 0; u < 4; u++) a[u] = As[o][lx + 16 * u];
#pragma unroll
            for (int u = 0; u < 4; u++) bb[u] = Bs[ly + 16 * u][o];
#pragma unroll
            for (int y = 0; y < 4; y++)
#pragma unroll
                for (int x = 0; x < 4; x++) acc[y][x] += a[x] * bb[y];
        }
        __syncthreads();
    }
#pragma unroll
    for (int y = 0; y < 4; y++) {
        int l = ly + 16 * y;
#pragma unroll
        for (int x = 0; x < 4; x++) {
            int i = i0 + lx + 16 * x;
            g_effw[((size_t)j * NL + l) * ND + i] = acc[y][x];
        }
    }
}

__global__ void effb_kernel(const float* __restrict__ cls_w,
                            const float* __restrict__ conv_b,
                            const float* __restrict__ cls_b) {
    int tid = threadIdx.x;
    int k = tid >> 6, l = tid & 63;
    float s = 0.f;
    for (int o = 0; o < ND; o++) s += cls_w[l * ND + o] * conv_b[k * ND + o];
    g_effb[k * NL + l] = s + cls_b[l];
}

// ---------------------------------------------------------------------------
// fp32 -> bf16 conversions
// ---------------------------------------------------------------------------
__global__ void __launch_bounds__(256) cvtA_kernel(const float* __restrict__ src) {
    size_t i = (size_t)blockIdx.x * 256 + threadIdx.x;   // pair index
    float2 v = ((const float2*)src)[i];
    ((__nv_bfloat162*)g_Ab)[i] = __nv_bfloat162(__float2bfloat16(v.x), __float2bfloat16(v.y));
}
// W[k][delta][l][d] = effw[j(k, h=k-delta)][l][d]
__global__ void __launch_bounds__(256) cvtB_kernel() {
    size_t i = (size_t)blockIdx.x * 256 + threadIdx.x;   // pair index over NJ*NL*256
    int jl = (int)(i >> 8);          // j*64 + l
    int cp = (int)(i & 255);
    int j = jl >> 6, l = jl & 63;
    int k = 0, rem = j;
    while (rem > k) { rem -= (k + 1); k++; }
    int h = rem, dl = k - h;
    float2 v = ((const float2*)g_effw)[i];
    __nv_bfloat162* dst = (__nv_bfloat162*)g_Bls + (((size_t)(k * 8 + dl) * NL + l) * (ND / 2));
    dst[cp] = __nv_bfloat162(__float2bfloat16(v.x), __float2bfloat16(v.y));
}

// ---------------------------------------------------------------------------
// Fused segment-score GEMM: one CTA per (128-row M tile, k).
//   ls[bs,k,l] = sum_{delta<=k} sum_d Ab[bs-delta,d] * W[k,delta,l,d]   (+mask)
// A smem tile: 136 rows (m0-7 .. m0+127) x 64 bf16 per d-chunk, ring of 3.
// B chunk: 64 l x 64 d, ring of 4. mma.sync m16n8k16 bf16.
// ---------------------------------------------------------------------------
#define AROWS 136
#define ABUF (AROWS * 128)       // 17408 B
#define BBUF (64 * 128)          // 8192 B
#define SM_LS (3 * ABUF + 4 * BBUF)   // 84992 B

__global__ void __launch_bounds__(256) lsmma_kernel(const int* __restrict__ mask) {
    extern __shared__ __align__(1024) char sm[];
    __shared__ int sMask[128];
    int tid = threadIdx.x, wid = tid >> 5, lane = tid & 31;
    int m0 = blockIdx.x * 128;
    int k = 7 - (int)blockIdx.y;        // heavy k first
    int kp1 = k + 1, C = 8 * kp1;
    uint32_t sA = smem_u32(sm);
    uint32_t sB = sA + 3 * ABUF;

    for (int i = tid; i < 128; i += 256) sMask[i] = mask[m0 + i];

    auto loadA = [&](int dc) {
        uint32_t base = sA + (uint32_t)((dc % 3) * ABUF);
#pragma unroll
        for (int it = 0; it < 5; ++it) {
            int i = tid + it * 256;
            if (i < 135 * 8) {
                int r = i >> 3, c8 = i & 7;
                int gr = m0 - 7 + r;
                gr = gr < 0 ? 0 : gr;
                uint32_t dst = base + (uint32_t)(r * 128 + ((c8 ^ (r & 7)) * 16));
                const void* src = g_Ab + (size_t)gr * ND + dc * 64 + c8 * 8;
                asm volatile("cp.async.ca.shared.global [%0], [%1], 16;" :: "r"(dst), "l"(src));
            }
        }
    };
    auto loadB = [&](int c, int dc, int dl) {
        uint32_t base = sB + (uint32_t)((c & 3) * BBUF);
#pragma unroll
        for (int it = 0; it < 2; ++it) {
            int i = tid + it * 256;
            int r = i >> 3, c8 = i & 7;
            uint32_t dst = base + (uint32_t)(r * 128 + ((c8 ^ (r & 7)) * 16));
            const void* src = g_Bls + ((size_t)(k * 8 + dl) * NL + r) * ND + dc * 64 + c8 * 8;
            asm volatile("cp.async.ca.shared.global [%0], [%1], 16;" :: "r"(dst), "l"(src));
        }
    };

    int ldc = 0, ldl = 0;
#pragma unroll
    for (int pre = 0; pre < 2; ++pre) {
        if (ldl == 0) loadA(ldc);
        loadB(pre, ldc, ldl);
        asm volatile("cp.async.commit_group;");
        if (++ldl == kp1) { ldl = 0; ++ldc; }
    }

    float acc[2][4][4] = {};
    int mw = (wid >> 1) * 32, nw = (wid & 1) * 32;

    int dc = 0, dl = 0;
    for (int c = 0; c < C; ++c) {
        asm volatile("cp.async.wait_group 1;" ::: "memory");
        __syncthreads();
        if (c + 2 < C) {
            if (ldl == 0) loadA(ldc);
            loadB(c + 2, ldc, ldl);
            if (++ldl == kp1) { ldl = 0; ++ldc; }
        }
        asm volatile("cp.async.commit_group;");

        uint32_t Ab = sA + (uint32_t)((dc % 3) * ABUF);
        uint32_t Bb = sB + (uint32_t)((c & 3) * BBUF);
        int roff = 7 - dl;
#pragma unroll
        for (int ks = 0; ks < 4; ++ks) {
            int c16 = ks * 2 + (lane >> 4);
            uint32_t ar[2][4], br[2][4];
#pragma unroll
            for (int mt = 0; mt < 2; ++mt) {
                int row = mw + mt * 16 + (lane & 15) + roff;
                uint32_t addr = Ab + row * 128 + ((c16 ^ (row & 7)) * 16);
                asm volatile("ldmatrix.sync.aligned.m8n8.x4.shared.b16 {%0,%1,%2,%3}, [%4];"
                             : "=r"(ar[mt][0]), "=r"(ar[mt][1]), "=r"(ar[mt][2]), "=r"(ar[mt][3])
                             : "r"(addr));
            }
#pragma unroll
            for (int g = 0; g < 2; ++g) {
                int row = nw + g * 16 + (lane & 15);
                uint32_t addr = Bb + row * 128 + ((c16 ^ (row & 7)) * 16);
                asm volatile("ldmatrix.sync.aligned.m8n8.x4.shared.b16 {%0,%1,%2,%3}, [%4];"
                             : "=r"(br[g][0]), "=r"(br[g][1]), "=r"(br[g][2]), "=r"(br[g][3])
                             : "r"(addr));
            }
#pragma unroll
            for (int mt = 0; mt < 2; ++mt)
#pragma unroll
                for (int nn = 0; nn < 4; ++nn) {
                    int g = nn >> 1, s2 = nn & 1;
                    asm volatile(
                        "mma.sync.aligned.m16n8k16.row.col.f32.bf16.bf16.f32 "
                        "{%0,%1,%2,%3},{%4,%5,%6,%7},{%8,%9},{%0,%1,%2,%3};"
                        : "+f"(acc[mt][nn][0]), "+f"(acc[mt][nn][1]),
                          "+f"(acc[mt][nn][2]), "+f"(acc[mt][nn][3])
                        : "r"(ar[mt][0]), "r"(ar[mt][1]), "r"(ar[mt][2]), "r"(ar[mt][3]),
                          "r"(br[g][s2]), "r"(br[g][s2 + 2]));
                }
        }
        if (++dl == kp1) { dl = 0; ++dc; }
    }

    // epilogue: mask + store ls (bias added later in dp)
#pragma unroll
    for (int mt = 0; mt < 2; ++mt) {
#pragma unroll
        for (int nn = 0; nn < 4; ++nn) {
            int col = nw + nn * 8 + (lane & 3) * 2;
#pragma unroll
            for (int half = 0; half < 2; ++half) {
                int r = mw + mt * 16 + (lane >> 2) + half * 8;
                int bs = m0 + r, s = bs & (NS - 1);
                bool okr = (sMask[r] == 1) && (k <= s);
                float a0 = acc[mt][nn][half * 2 + 0];
                float a1 = acc[mt][nn][half * 2 + 1];
                float2 v;
                v.x = (okr && col != 0) ? a0 : NEGC;
                v.y = okr ? a1 : NEGC;
                *(float2*)&g_ls[((size_t)bs * NK + k) * NL + col] = v;
            }
        }
    }
}

// ---------------------------------------------------------------------------
// Kernel C: semi-CRF DP, 1 block/batch, 1 barrier/step, stale-max normalize.
// Bias (effb) folded in here as registers.
// ---------------------------------------------------------------------------
__global__ void __launch_bounds__(256) dp_kernel(const int* __restrict__ mask,
                                                 const float* __restrict__ T,
                                                 const float* __restrict__ TFB,
                                                 const float* __restrict__ TTE,
                                                 float* __restrict__ out) {
    int b = blockIdx.x;
    int tid = threadIdx.x;
    int lane = tid & 31, warp = tid >> 5;
    int l = tid >> 2, q = tid & 3;

    __shared__ __align__(16) float sLs[4][512];
    __shared__ float sMring[8][65];
    __shared__ float sE[2][64];
    __shared__ float sWmax[2][8];
    __shared__ float sTFB[64], sTTE[64], sRed[8];
    __shared__ float sMaxS;
    __shared__ int sMask[256], sLen;

    float rT[16];
#pragma unroll
    for (int jj = 0; jj < 16; ++jj) rT[jj] = __expf(T[l * NL + q * 16 + jj]);
    float rB0 = g_effb[q * NL + l];
    float rB1 = g_effb[(q + 4) * NL + l];
    if (tid < 64) {
        sTFB[tid] = TFB[tid];
        sTTE[tid] = TTE[tid];
#pragma unroll
        for (int i = 0; i < 8; ++i) sMring[i][tid] = NEGC;
    }
    sMask[tid] = mask[b * NS + tid];
    if (tid == 0) sLen = 0;

    const float* lsb = g_ls + (size_t)b * NS * (NK * NL);
    unsigned sls = (unsigned)__cvta_generic_to_shared(&sLs[0][0]);
#pragma unroll
    for (int p = 0; p < 3; ++p) {
        asm volatile("cp.async.ca.shared.global [%0], [%1], 8;"
                     :: "r"(sls + (unsigned)((p * 512 + tid * 2) * 4)),
                        "l"(lsb + p * 512 + tid * 2));
        asm volatile("cp.async.commit_group;");
    }
    asm volatile("cp.async.wait_group 2;" ::: "memory");
    __syncthreads();

    float N = 0.f;
    for (int t = 0; t < NS; ++t) {
        int mv = sMask[t];
        const float* lst = &sLs[t & 3][0];
        float v0, v1;
        {
            int k = q;
            float lsv = lst[k * 64 + l] + rB0;
            v0 = (k == t) ? lsv + sTFB[l]
               : (k > t)  ? NEGC
               : (mv ? lsv + sMring[(t - 1 - k) & 7][l] : NEGC);
        }
        {
            int k = q + 4;
            float lsv = lst[k * 64 + l] + rB1;
            v1 = (k == t) ? lsv + sTFB[l]
               : (k > t)  ? NEGC
               : (mv ? lsv + sMring[(t - 1 - k) & 7][l] : NEGC);
        }
        float e = __expf(v0 - N) + __expf(v1 - N);
        e += __shfl_xor_sync(~0u, e, 1);
        e += __shfl_xor_sync(~0u, e, 2);
        if (q == 0) sE[t & 1][l] = e;
        float wm = e;
        wm = fmaxf(wm, __shfl_xor_sync(~0u, wm, 4));
        wm = fmaxf(wm, __shfl_xor_sync(~0u, wm, 8));
        wm = fmaxf(wm, __shfl_xor_sync(~0u, wm, 16));
        if (lane == 0) sWmax[t & 1][warp] = wm;

        if (t + 3 < NS) {
            asm volatile("cp.async.ca.shared.global [%0], [%1], 8;"
                         :: "r"(sls + (unsigned)((((t + 3) & 3) * 512 + tid * 2) * 4)),
                            "l"(lsb + (size_t)(t + 3) * 512 + tid * 2));
        }
        asm volatile("cp.async.commit_group;");
        asm volatile("cp.async.wait_group 2;" ::: "memory");
        __syncthreads();

        float p = 0.f;
        const float* se = &sE[t & 1][q * 16];
#pragma unroll
        for (int jj = 0; jj < 16; ++jj) p += rT[jj] * se[jj];
        p += __shfl_xor_sync(~0u, p, 1);
        p += __shfl_xor_sync(~0u, p, 2);
        float Mnew = fmaxf(__logf(p) + N, -1e30f);
        if (q == 0) {
            sMring[t & 7][l] = Mnew;
            g_M[((size_t)b * NS + t) * NL + l] = Mnew;
        }
        float me = sWmax[t & 1][0];
#pragma unroll
        for (int w = 1; w < 8; ++w) me = fmaxf(me, sWmax[t & 1][w]);
        N += __logf(fmaxf(me, 1e-30f));
        __syncwarp();
    }

    {
        int mvv = sMask[tid];
#pragma unroll
        for (int o = 16; o > 0; o >>= 1) mvv += __shfl_xor_sync(~0u, mvv, o);
        if (lane == 0) atomicAdd(&sLen, mvv);
    }
    __syncthreads();
    int len = sLen;

    float vv[2];
#pragma unroll
    for (int u = 0; u < 2; ++u) {
        int k = q + 4 * u;
        int tk = len - 1 - k;
        int tix = (tk >= 0) ? tk : (NS - 1);
        float lsv = lsb[(size_t)tix * (NK * NL) + k * NL + l] + (u == 0 ? rB0 : rB1);
        float gv;
        if (k == tix)      gv = lsv + sTFB[l];
        else if (k > tix)  gv = NEGC;
        else               gv = (sMask[tix] == 1)
                                  ? lsv + g_M[((size_t)b * NS + (tix - 1 - k)) * NL + l]
                                  : NEGC;
        vv[u] = gv + sTTE[l];
    }
    float mx = fmaxf(vv[0], vv[1]);
#pragma unroll
    for (int o = 16; o > 0; o >>= 1) mx = fmaxf(mx, __shfl_xor_sync(~0u, mx, o));
    if (lane == 0) sRed[warp] = mx;
    __syncthreads();
    if (tid == 0) {
        float m = sRed[0];
#pragma unroll
        for (int w = 1; w < 8; ++w) m = fmaxf(m, sRed[w]);
        sMaxS = m;
    }
    __syncthreads();
    float gm = sMaxS;
    float e2 = __expf(vv[0] - gm) + __expf(vv[1] - gm);
#pragma unroll
    for (int o = 16; o > 0; o >>= 1) e2 += __shfl_xor_sync(~0u, e2, o);
    if (lane == 0) sRed[warp] = e2;
    __syncthreads();
    if (tid == 0) {
        float ssum = 0.f;
#pragma unroll
        for (int w = 0; w < 8; ++w) ssum += sRed[w];
        out[b] = __logf(ssum) + gm;
    }
}

// ---------------------------------------------------------------------------
extern "C" void kernel_launch(void* const* d_in, const int* in_sizes, int n_in,
                              void* d_out, int out_size) {
    const float* word_rep = (const float*)d_in[0];
    const int*   mask     = (const int*)  d_in[1];
    const float* conv_w   = (const float*)d_in[2];
    const float* conv_b   = (const float*)d_in[3];
    const float* cls_w    = (const float*)d_in[4];
    const float* cls_b    = (const float*)d_in[5];
    const float* T        = (const float*)d_in[6];
    const float* TFB      = (const float*)d_in[7];
    const float* TTE      = (const float*)d_in[8];
    float* out = (float*)d_out;

    cudaFuncSetAttribute(lsmma_kernel, cudaFuncAttributeMaxDynamicSharedMemorySize, SM_LS);

    cvtA_kernel<<<(NROW * ND / 2) / 256, 256>>>(word_rep);        // launch 0
    eff_kernel<<<dim3(NJ, 8), 256>>>(conv_w, cls_w);              // launch 1
    cvtB_kernel<<<(NJ * NL * ND / 2) / 256, 256>>>();             // launch 2
    lsmma_kernel<<<dim3(NROW / 128, NK), 256, SM_LS>>>(mask);     // launch 3 (profiled)
    effb_kernel<<<1, NK * NL>>>(cls_w, conv_b, cls_b);            // launch 4
    dp_kernel<<<NB, 256>>>(mask, T, TFB, TTE, out);               // launch 5
}